// round 2
// baseline (speedup 1.0000x reference)
#include <cuda_runtime.h>
#include <math.h>

#define N_NODES 4096
#define N_GRAPH 8
#define N_ROWS  (N_GRAPH * N_NODES)   // 32768
#define LOG2E   1.4426950408889634f

// Persistent scratch (no allocations allowed).
__device__ float4 g_table[N_NODES];          // swizzled: [(j&3)*1024 + (j>>2)] = (d'_j, Wh0, Wh1, Wh2)
__device__ float  g_sprime[N_NODES];         // s_i * log2(e)
__device__ float  g_h[N_GRAPH * N_NODES * 3];// elu(attn @ Wh), flattened [B, N*3]

__device__ __forceinline__ float ex2f_fast(float x) {
    float r; asm("ex2.approx.ftz.f32 %0, %1;" : "=f"(r) : "f"(x)); return r;
}

// ---------------------------------------------------------------------------
// Kernel 1: Wh = emb @ W, s = Wh@a[:3], d = Wh@a[3:], build swizzled table.
// ---------------------------------------------------------------------------
__global__ void prep_kernel(const float* __restrict__ emb,
                            const float* __restrict__ W,
                            const float* __restrict__ a) {
    __shared__ float sW[384];
    __shared__ float sa[6];
    int tid = threadIdx.x;
    for (int k = tid; k < 384; k += blockDim.x) sW[k] = W[k];   // FIXED: full load
    if (tid < 6) sa[tid] = a[tid];
    __syncthreads();

    int i = blockIdx.x * blockDim.x + tid;   // 0..4095
    const float4* e4 = reinterpret_cast<const float4*>(emb + (size_t)i * 128);
    float w0 = 0.f, w1 = 0.f, w2 = 0.f;
#pragma unroll
    for (int f4 = 0; f4 < 32; ++f4) {
        float4 e = e4[f4];
        int f = f4 * 4;
        w0 = fmaf(e.x, sW[(f+0)*3+0], w0); w1 = fmaf(e.x, sW[(f+0)*3+1], w1); w2 = fmaf(e.x, sW[(f+0)*3+2], w2);
        w0 = fmaf(e.y, sW[(f+1)*3+0], w0); w1 = fmaf(e.y, sW[(f+1)*3+1], w1); w2 = fmaf(e.y, sW[(f+1)*3+2], w2);
        w0 = fmaf(e.z, sW[(f+2)*3+0], w0); w1 = fmaf(e.z, sW[(f+2)*3+1], w1); w2 = fmaf(e.z, sW[(f+2)*3+2], w2);
        w0 = fmaf(e.w, sW[(f+3)*3+0], w0); w1 = fmaf(e.w, sW[(f+3)*3+1], w1); w2 = fmaf(e.w, sW[(f+3)*3+2], w2);
    }
    float s = w0*sa[0] + w1*sa[1] + w2*sa[2];
    float d = w0*sa[3] + w1*sa[4] + w2*sa[5];
    g_sprime[i] = s * LOG2E;
    g_table[(i & 3) * 1024 + (i >> 2)] = make_float4(d * LOG2E, w0, w1, w2);
}

// ---------------------------------------------------------------------------
// Kernel 2: fused masked-softmax attention row reduction.
// One warp per (graph,row). adj read int4-vectorized; per-j data from a
// conflict-free swizzled smem table. w = exp2(max(x',0.2x')) * mask.
// ---------------------------------------------------------------------------
__global__ void __launch_bounds__(256, 3)
gat_kernel(const int* __restrict__ adj) {
    extern __shared__ float4 tbl[];   // 4096 float4 = 64 KB
    int tid = threadIdx.x;
    for (int idx = tid; idx < N_NODES; idx += blockDim.x)
        tbl[idx] = g_table[idx];
    __syncthreads();

    const float4* t0 = tbl;
    const float4* t1 = tbl + 1024;
    const float4* t2 = tbl + 2048;
    const float4* t3 = tbl + 3072;

    int lane = tid & 31;
    int warp = tid >> 5;
    int wg = blockIdx.x * (blockDim.x >> 5) + warp;
    int total_warps = gridDim.x * (blockDim.x >> 5);

    for (int row = wg; row < N_ROWS; row += total_warps) {
        int i = row & (N_NODES - 1);
        float sp = __ldg(&g_sprime[i]);
        const int4* arow = reinterpret_cast<const int4*>(adj) + (size_t)row * 1024;

        float sum = 0.f, acc0 = 0.f, acc1 = 0.f, acc2 = 0.f;

#define PROC(mm, g) do {                                   \
        float x_ = sp + (g).x;                             \
        float y_ = fmaxf(x_, 0.2f * x_);                   \
        float w_ = ex2f_fast(y_) * (float)(mm);            \
        sum  += w_;                                        \
        acc0 = fmaf(w_, (g).y, acc0);                      \
        acc1 = fmaf(w_, (g).z, acc1);                      \
        acc2 = fmaf(w_, (g).w, acc2); } while (0)

#pragma unroll 4
        for (int q = lane; q < 1024; q += 32) {
            int4 m = arow[q];
            float4 gA = t0[q];
            float4 gB = t1[q];
            float4 gC = t2[q];
            float4 gD = t3[q];
            PROC(m.x, gA);
            PROC(m.y, gB);
            PROC(m.z, gC);
            PROC(m.w, gD);
        }
#undef PROC

#pragma unroll
        for (int off = 16; off; off >>= 1) {
            sum  += __shfl_xor_sync(0xffffffffu, sum,  off);
            acc0 += __shfl_xor_sync(0xffffffffu, acc0, off);
            acc1 += __shfl_xor_sync(0xffffffffu, acc1, off);
            acc2 += __shfl_xor_sync(0xffffffffu, acc2, off);
        }

        if (sum == 0.0f) {
            // Reference: softmax over all-NEG_INF row = uniform 1/N over ALL j.
            acc0 = acc1 = acc2 = 0.f;
            for (int q = lane; q < 1024; q += 32) {
                float4 gA = t0[q], gB = t1[q], gC = t2[q], gD = t3[q];
                acc0 += gA.y + gB.y + gC.y + gD.y;
                acc1 += gA.z + gB.z + gC.z + gD.z;
                acc2 += gA.w + gB.w + gC.w + gD.w;
            }
#pragma unroll
            for (int off = 16; off; off >>= 1) {
                acc0 += __shfl_xor_sync(0xffffffffu, acc0, off);
                acc1 += __shfl_xor_sync(0xffffffffu, acc1, off);
                acc2 += __shfl_xor_sync(0xffffffffu, acc2, off);
            }
            sum = (float)N_NODES;
        }

        if (lane == 0) {
            float inv = 1.0f / sum;
            float h0 = acc0 * inv, h1 = acc1 * inv, h2 = acc2 * inv;
            h0 = h0 > 0.f ? h0 : expm1f(h0);
            h1 = h1 > 0.f ? h1 : expm1f(h1);
            h2 = h2 > 0.f ? h2 : expm1f(h2);
            float* hp = g_h + (size_t)(row >> 12) * (N_NODES * 3) + (size_t)i * 3;
            hp[0] = h0; hp[1] = h1; hp[2] = h2;
        }
    }
}

// ---------------------------------------------------------------------------
// Kernel 3: out[b,o] = sum_k g_h[b,k] * fc1_w[o,k] + fc1_b[o]
// ---------------------------------------------------------------------------
__global__ void __launch_bounds__(128)
fc_kernel(const float* __restrict__ fw, const float* __restrict__ fb,
          float* __restrict__ out) {
    int o = blockIdx.x;               // 0..99
    const float* wrow = fw + (size_t)o * (N_NODES * 3);
    float acc[N_GRAPH];
#pragma unroll
    for (int b = 0; b < N_GRAPH; ++b) acc[b] = 0.f;

    for (int k = threadIdx.x; k < N_NODES * 3; k += 128) {
        float wv = __ldg(wrow + k);
#pragma unroll
        for (int b = 0; b < N_GRAPH; ++b)
            acc[b] = fmaf(wv, g_h[(size_t)b * (N_NODES * 3) + k], acc[b]);
    }

#pragma unroll
    for (int b = 0; b < N_GRAPH; ++b)
#pragma unroll
        for (int off = 16; off; off >>= 1)
            acc[b] += __shfl_xor_sync(0xffffffffu, acc[b], off);

    __shared__ float red[N_GRAPH][4];
    int lane = threadIdx.x & 31, w = threadIdx.x >> 5;
    if (lane == 0) {
#pragma unroll
        for (int b = 0; b < N_GRAPH; ++b) red[b][w] = acc[b];
    }
    __syncthreads();
    if (threadIdx.x < N_GRAPH) {
        float v = red[threadIdx.x][0] + red[threadIdx.x][1] +
                  red[threadIdx.x][2] + red[threadIdx.x][3] + fb[o];
        out[threadIdx.x * 100 + o] = v;
    }
}

// ---------------------------------------------------------------------------
extern "C" void kernel_launch(void* const* d_in, const int* in_sizes, int n_in,
                              void* d_out, int out_size) {
    const int*   adj = (const int*)d_in[0];
    const float* emb = (const float*)d_in[1];
    const float* W   = (const float*)d_in[2];
    const float* a   = (const float*)d_in[3];
    const float* fw  = (const float*)d_in[4];
    const float* fb  = (const float*)d_in[5];
    float* out = (float*)d_out;

    cudaFuncSetAttribute(gat_kernel, cudaFuncAttributeMaxDynamicSharedMemorySize, 65536);

    prep_kernel<<<16, 256>>>(emb, W, a);
    gat_kernel<<<444, 256, 65536>>>(adj);
    fc_kernel<<<100, 128>>>(fw, fb, out);
}

// round 3
// speedup vs baseline: 1.1490x; 1.1490x over previous
#include <cuda_runtime.h>
#include <math.h>

#define N_NODES 4096
#define N_GRAPH 8
#define LOG2E   1.4426950408889634f
#define GSTRIDE 4194304   // int4 elements per graph (4096*4096/4)

// Persistent scratch (no allocations allowed).
__device__ float4 g_table[N_NODES];           // swizzled: [(j&3)*1024 + (j>>2)] = (d'_j, Wh0, Wh1, Wh2)
__device__ float  g_sprime[N_NODES];          // s_i * log2(e)
__device__ float  g_fallback[3];              // elu(mean_j Wh_j) for all-masked rows
__device__ float  g_h[N_GRAPH * N_NODES * 3]; // elu(attn @ Wh), [B][N*3]

__device__ __forceinline__ float ex2f_fast(float x) {
    float r; asm("ex2.approx.ftz.f32 %0, %1;" : "=f"(r) : "f"(x)); return r;
}

// ---------------------------------------------------------------------------
// Kernel 1: Wh = emb @ W, s,d, build swizzled table. 4 lanes per node.
// ---------------------------------------------------------------------------
__global__ void __launch_bounds__(256)
prep_kernel(const float* __restrict__ emb,
            const float* __restrict__ W,
            const float* __restrict__ a) {
    __shared__ float sW[384];
    __shared__ float sa[6];
    int tid = threadIdx.x;
    for (int k = tid; k < 384; k += 256) sW[k] = W[k];
    if (tid < 6) sa[tid] = a[tid];
    __syncthreads();

    int t  = blockIdx.x * 256 + tid;      // 0..16383
    int i  = t >> 2;                      // node
    int qd = t & 3;                       // quarter of the feature dim
    const float4* e4 = reinterpret_cast<const float4*>(emb + (size_t)i * 128) + qd * 8;
    float w0 = 0.f, w1 = 0.f, w2 = 0.f;
#pragma unroll
    for (int f4 = 0; f4 < 8; ++f4) {
        float4 e = e4[f4];
        int f = (qd * 8 + f4) * 4;
        w0 = fmaf(e.x, sW[(f+0)*3+0], w0); w1 = fmaf(e.x, sW[(f+0)*3+1], w1); w2 = fmaf(e.x, sW[(f+0)*3+2], w2);
        w0 = fmaf(e.y, sW[(f+1)*3+0], w0); w1 = fmaf(e.y, sW[(f+1)*3+1], w1); w2 = fmaf(e.y, sW[(f+1)*3+2], w2);
        w0 = fmaf(e.z, sW[(f+2)*3+0], w0); w1 = fmaf(e.z, sW[(f+2)*3+1], w1); w2 = fmaf(e.z, sW[(f+2)*3+2], w2);
        w0 = fmaf(e.w, sW[(f+3)*3+0], w0); w1 = fmaf(e.w, sW[(f+3)*3+1], w1); w2 = fmaf(e.w, sW[(f+3)*3+2], w2);
    }
#pragma unroll
    for (int off = 1; off <= 2; off <<= 1) {
        w0 += __shfl_xor_sync(0xffffffffu, w0, off);
        w1 += __shfl_xor_sync(0xffffffffu, w1, off);
        w2 += __shfl_xor_sync(0xffffffffu, w2, off);
    }
    if (qd == 0) {
        float s = w0*sa[0] + w1*sa[1] + w2*sa[2];
        float d = w0*sa[3] + w1*sa[4] + w2*sa[5];
        g_sprime[i] = s * LOG2E;
        g_table[(i & 3) * 1024 + (i >> 2)] = make_float4(d * LOG2E, w0, w1, w2);
    }
}

// ---------------------------------------------------------------------------
// Kernel 2: fallback for all-masked rows: elu(mean_j Wh_j)
// ---------------------------------------------------------------------------
__global__ void __launch_bounds__(256)
mean_kernel() {
    int tid = threadIdx.x;
    float m0 = 0.f, m1 = 0.f, m2 = 0.f;
    for (int idx = tid; idx < N_NODES; idx += 256) {
        float4 g = g_table[idx];
        m0 += g.y; m1 += g.z; m2 += g.w;
    }
#pragma unroll
    for (int off = 16; off; off >>= 1) {
        m0 += __shfl_xor_sync(0xffffffffu, m0, off);
        m1 += __shfl_xor_sync(0xffffffffu, m1, off);
        m2 += __shfl_xor_sync(0xffffffffu, m2, off);
    }
    __shared__ float red[3][8];
    int lane = tid & 31, w = tid >> 5;
    if (lane == 0) { red[0][w] = m0; red[1][w] = m1; red[2][w] = m2; }
    __syncthreads();
    if (tid == 0) {
        float t0 = 0.f, t1 = 0.f, t2 = 0.f;
#pragma unroll
        for (int k = 0; k < 8; ++k) { t0 += red[0][k]; t1 += red[1][k]; t2 += red[2][k]; }
        t0 *= (1.0f / N_NODES); t1 *= (1.0f / N_NODES); t2 *= (1.0f / N_NODES);
        g_fallback[0] = t0 > 0.f ? t0 : expm1f(t0);
        g_fallback[1] = t1 > 0.f ? t1 : expm1f(t1);
        g_fallback[2] = t2 > 0.f ? t2 : expm1f(t2);
    }
}

// ---------------------------------------------------------------------------
// Kernel 3: fused GAT. One warp per node-row i, ALL 8 graphs at once.
// exp/table work amortized 8x; per-(b,j) element only sel+add+3 FFMA.
// ---------------------------------------------------------------------------
__global__ void __launch_bounds__(256, 2)
gat8_kernel(const int* __restrict__ adj) {
    extern __shared__ float4 tbl[];   // 4096 float4 = 64 KB
    int tid = threadIdx.x;
    for (int idx = tid; idx < N_NODES; idx += 256)
        tbl[idx] = g_table[idx];
    __syncthreads();

    const float4* t0 = tbl;
    const float4* t1 = tbl + 1024;
    const float4* t2 = tbl + 2048;
    const float4* t3 = tbl + 3072;

    int lane = tid & 31;
    int warp = tid >> 5;
    int wg = blockIdx.x * 8 + warp;   // 0..2047

#pragma unroll
    for (int r = 0; r < 2; ++r) {
        int i = wg + r * 2048;
        float sp = __ldg(&g_sprime[i]);
        const int4* arow = reinterpret_cast<const int4*>(adj) + (size_t)i * 1024;

        float sum[N_GRAPH], a0[N_GRAPH], a1[N_GRAPH], a2[N_GRAPH];
#pragma unroll
        for (int b = 0; b < N_GRAPH; ++b) { sum[b] = 0.f; a0[b] = 0.f; a1[b] = 0.f; a2[b] = 0.f; }

        for (int q = lane; q < 1024; q += 32) {
            int4 m[N_GRAPH];
#pragma unroll
            for (int b = 0; b < N_GRAPH; ++b)
                m[b] = arow[(size_t)b * GSTRIDE + q];

            float4 gA = t0[q];
            float4 gB = t1[q];
            float4 gC = t2[q];
            float4 gD = t3[q];

            float xA = sp + gA.x; float wA = ex2f_fast(fmaxf(xA, 0.2f * xA));
            float xB = sp + gB.x; float wB = ex2f_fast(fmaxf(xB, 0.2f * xB));
            float xC = sp + gC.x; float wC = ex2f_fast(fmaxf(xC, 0.2f * xC));
            float xD = sp + gD.x; float wD = ex2f_fast(fmaxf(xD, 0.2f * xD));

#pragma unroll
            for (int b = 0; b < N_GRAPH; ++b) {
                float wx = m[b].x ? wA : 0.f;
                float wy = m[b].y ? wB : 0.f;
                float wz = m[b].z ? wC : 0.f;
                float ww = m[b].w ? wD : 0.f;
                sum[b] += (wx + wy) + (wz + ww);
                a0[b] = fmaf(wx, gA.y, a0[b]); a0[b] = fmaf(wy, gB.y, a0[b]);
                a0[b] = fmaf(wz, gC.y, a0[b]); a0[b] = fmaf(ww, gD.y, a0[b]);
                a1[b] = fmaf(wx, gA.z, a1[b]); a1[b] = fmaf(wy, gB.z, a1[b]);
                a1[b] = fmaf(wz, gC.z, a1[b]); a1[b] = fmaf(ww, gD.z, a1[b]);
                a2[b] = fmaf(wx, gA.w, a2[b]); a2[b] = fmaf(wy, gB.w, a2[b]);
                a2[b] = fmaf(wz, gC.w, a2[b]); a2[b] = fmaf(ww, gD.w, a2[b]);
            }
        }

#pragma unroll
        for (int b = 0; b < N_GRAPH; ++b) {
#pragma unroll
            for (int off = 16; off; off >>= 1) {
                sum[b] += __shfl_xor_sync(0xffffffffu, sum[b], off);
                a0[b]  += __shfl_xor_sync(0xffffffffu, a0[b],  off);
                a1[b]  += __shfl_xor_sync(0xffffffffu, a1[b],  off);
                a2[b]  += __shfl_xor_sync(0xffffffffu, a2[b],  off);
            }
        }

        if (lane == 0) {
#pragma unroll
            for (int b = 0; b < N_GRAPH; ++b) {
                float* hp = g_h + (size_t)b * (N_NODES * 3) + (size_t)i * 3;
                if (sum[b] == 0.0f) {
                    hp[0] = __ldg(&g_fallback[0]);
                    hp[1] = __ldg(&g_fallback[1]);
                    hp[2] = __ldg(&g_fallback[2]);
                } else {
                    float inv = 1.0f / sum[b];
                    float h0 = a0[b] * inv, h1 = a1[b] * inv, h2 = a2[b] * inv;
                    hp[0] = h0 > 0.f ? h0 : expm1f(h0);
                    hp[1] = h1 > 0.f ? h1 : expm1f(h1);
                    hp[2] = h2 > 0.f ? h2 : expm1f(h2);
                }
            }
        }
    }
}

// ---------------------------------------------------------------------------
// Kernel 4: out[b,o] = sum_k g_h[b,k] * fc1_w[o,k] + fc1_b[o]
// ---------------------------------------------------------------------------
__global__ void __launch_bounds__(256)
fc_kernel(const float* __restrict__ fw, const float* __restrict__ fb,
          float* __restrict__ out) {
    int o = blockIdx.x;               // 0..99
    const float* wrow = fw + (size_t)o * (N_NODES * 3);
    float acc[N_GRAPH];
#pragma unroll
    for (int b = 0; b < N_GRAPH; ++b) acc[b] = 0.f;

    for (int k = threadIdx.x; k < N_NODES * 3; k += 256) {
        float wv = __ldg(wrow + k);
#pragma unroll
        for (int b = 0; b < N_GRAPH; ++b)
            acc[b] = fmaf(wv, g_h[(size_t)b * (N_NODES * 3) + k], acc[b]);
    }

#pragma unroll
    for (int b = 0; b < N_GRAPH; ++b)
#pragma unroll
        for (int off = 16; off; off >>= 1)
            acc[b] += __shfl_xor_sync(0xffffffffu, acc[b], off);

    __shared__ float red[N_GRAPH][8];
    int lane = threadIdx.x & 31, w = threadIdx.x >> 5;
    if (lane == 0) {
#pragma unroll
        for (int b = 0; b < N_GRAPH; ++b) red[b][w] = acc[b];
    }
    __syncthreads();
    if (threadIdx.x < N_GRAPH) {
        float v = fb[o];
#pragma unroll
        for (int k = 0; k < 8; ++k) v += red[threadIdx.x][k];
        out[threadIdx.x * 100 + o] = v;
    }
}

// ---------------------------------------------------------------------------
extern "C" void kernel_launch(void* const* d_in, const int* in_sizes, int n_in,
                              void* d_out, int out_size) {
    const int*   adj = (const int*)d_in[0];
    const float* emb = (const float*)d_in[1];
    const float* W   = (const float*)d_in[2];
    const float* a   = (const float*)d_in[3];
    const float* fw  = (const float*)d_in[4];
    const float* fb  = (const float*)d_in[5];
    float* out = (float*)d_out;

    cudaFuncSetAttribute(gat8_kernel, cudaFuncAttributeMaxDynamicSharedMemorySize, 65536);

    prep_kernel<<<64, 256>>>(emb, W, a);
    mean_kernel<<<1, 256>>>();
    gat8_kernel<<<256, 256, 65536>>>(adj);
    fc_kernel<<<100, 256>>>(fw, fb, out);
}

// round 4
// speedup vs baseline: 1.3276x; 1.1554x over previous
#include <cuda_runtime.h>
#include <math.h>

#define N_NODES 4096
#define N_GRAPH 8
#define LOG2E   1.4426950408889634f
#define GSTRIDE 4194304   // int4 elements per graph (4096*4096/4)
#define KTOT    (N_NODES * 3)   // 12288
#define KCHUNK  1536            // KTOT / 8

// Persistent scratch (no allocations allowed).
__device__ float4 g_table[N_NODES];           // swizzled: [(j&3)*1024 + (j>>2)] = (d'_j, Wh0, Wh1, Wh2)
__device__ float  g_sprime[N_NODES];          // s_i * log2(e)
__device__ float  g_fallback[3];              // elu(mean_j Wh_j) for all-masked rows
__device__ float  g_h[N_GRAPH * KTOT];        // elu(attn @ Wh), [B][N*3]
__device__ float  g_fcpart[8 * 100 * N_GRAPH];// [chunk][o][b]

__device__ __forceinline__ float ex2f_fast(float x) {
    float r; asm("ex2.approx.ftz.f32 %0, %1;" : "=f"(r) : "f"(x)); return r;
}
__device__ __forceinline__ float maskf(int m, float w) {
    return __int_as_float((-m) & __float_as_int(w));
}

// ---------------------------------------------------------------------------
// Kernel 1: Wh = emb @ W, s,d, build swizzled table. 4 lanes per node.
// ---------------------------------------------------------------------------
__global__ void __launch_bounds__(256)
prep_kernel(const float* __restrict__ emb,
            const float* __restrict__ W,
            const float* __restrict__ a) {
    __shared__ float sW[384];
    __shared__ float sa[6];
    int tid = threadIdx.x;
    for (int k = tid; k < 384; k += 256) sW[k] = W[k];
    if (tid < 6) sa[tid] = a[tid];
    __syncthreads();

    int t  = blockIdx.x * 256 + tid;      // 0..16383
    int i  = t >> 2;                      // node
    int qd = t & 3;                       // quarter of the feature dim
    const float4* e4 = reinterpret_cast<const float4*>(emb + (size_t)i * 128) + qd * 8;
    float w0 = 0.f, w1 = 0.f, w2 = 0.f;
#pragma unroll
    for (int f4 = 0; f4 < 8; ++f4) {
        float4 e = e4[f4];
        int f = (qd * 8 + f4) * 4;
        w0 = fmaf(e.x, sW[(f+0)*3+0], w0); w1 = fmaf(e.x, sW[(f+0)*3+1], w1); w2 = fmaf(e.x, sW[(f+0)*3+2], w2);
        w0 = fmaf(e.y, sW[(f+1)*3+0], w0); w1 = fmaf(e.y, sW[(f+1)*3+1], w1); w2 = fmaf(e.y, sW[(f+1)*3+2], w2);
        w0 = fmaf(e.z, sW[(f+2)*3+0], w0); w1 = fmaf(e.z, sW[(f+2)*3+1], w1); w2 = fmaf(e.z, sW[(f+2)*3+2], w2);
        w0 = fmaf(e.w, sW[(f+3)*3+0], w0); w1 = fmaf(e.w, sW[(f+3)*3+1], w1); w2 = fmaf(e.w, sW[(f+3)*3+2], w2);
    }
#pragma unroll
    for (int off = 1; off <= 2; off <<= 1) {
        w0 += __shfl_xor_sync(0xffffffffu, w0, off);
        w1 += __shfl_xor_sync(0xffffffffu, w1, off);
        w2 += __shfl_xor_sync(0xffffffffu, w2, off);
    }
    if (qd == 0) {
        float s = w0*sa[0] + w1*sa[1] + w2*sa[2];
        float d = w0*sa[3] + w1*sa[4] + w2*sa[5];
        g_sprime[i] = s * LOG2E;
        g_table[(i & 3) * 1024 + (i >> 2)] = make_float4(d * LOG2E, w0, w1, w2);
    }
}

// ---------------------------------------------------------------------------
// Kernel 2: fallback for all-masked rows: elu(mean_j Wh_j)
// ---------------------------------------------------------------------------
__global__ void __launch_bounds__(256)
mean_kernel() {
    int tid = threadIdx.x;
    float m0 = 0.f, m1 = 0.f, m2 = 0.f;
    for (int idx = tid; idx < N_NODES; idx += 256) {
        float4 g = g_table[idx];
        m0 += g.y; m1 += g.z; m2 += g.w;
    }
#pragma unroll
    for (int off = 16; off; off >>= 1) {
        m0 += __shfl_xor_sync(0xffffffffu, m0, off);
        m1 += __shfl_xor_sync(0xffffffffu, m1, off);
        m2 += __shfl_xor_sync(0xffffffffu, m2, off);
    }
    __shared__ float red[3][8];
    int lane = tid & 31, w = tid >> 5;
    if (lane == 0) { red[0][w] = m0; red[1][w] = m1; red[2][w] = m2; }
    __syncthreads();
    if (tid == 0) {
        float t0 = 0.f, t1 = 0.f, t2 = 0.f;
#pragma unroll
        for (int k = 0; k < 8; ++k) { t0 += red[0][k]; t1 += red[1][k]; t2 += red[2][k]; }
        t0 *= (1.0f / N_NODES); t1 *= (1.0f / N_NODES); t2 *= (1.0f / N_NODES);
        g_fallback[0] = t0 > 0.f ? t0 : expm1f(t0);
        g_fallback[1] = t1 > 0.f ? t1 : expm1f(t1);
        g_fallback[2] = t2 > 0.f ? t2 : expm1f(t2);
    }
}

// ---------------------------------------------------------------------------
// Kernel 3: fused GAT. One warp per node-row i, ALL 8 graphs at once.
// Mask applied as (-m)&bits on the alu pipe; q-loop unrolled 2x for MLP.
// ---------------------------------------------------------------------------
__global__ void __launch_bounds__(256, 2)
gat8_kernel(const int* __restrict__ adj) {
    extern __shared__ float4 tbl[];   // 4096 float4 = 64 KB
    int tid = threadIdx.x;
    for (int idx = tid; idx < N_NODES; idx += 256)
        tbl[idx] = g_table[idx];
    __syncthreads();

    const float4* t0 = tbl;
    const float4* t1 = tbl + 1024;
    const float4* t2 = tbl + 2048;
    const float4* t3 = tbl + 3072;

    int lane = tid & 31;
    int warp = tid >> 5;
    int wg = blockIdx.x * 8 + warp;   // 0..2047

#pragma unroll
    for (int r = 0; r < 2; ++r) {
        int i = wg + r * 2048;
        float sp = __ldg(&g_sprime[i]);
        const int4* arow = reinterpret_cast<const int4*>(adj) + (size_t)i * 1024;

        float sum[N_GRAPH], a0[N_GRAPH], a1[N_GRAPH], a2[N_GRAPH];
#pragma unroll
        for (int b = 0; b < N_GRAPH; ++b) { sum[b] = 0.f; a0[b] = 0.f; a1[b] = 0.f; a2[b] = 0.f; }

#pragma unroll 2
        for (int q = lane; q < 1024; q += 32) {
            int4 m[N_GRAPH];
#pragma unroll
            for (int b = 0; b < N_GRAPH; ++b)
                m[b] = arow[(size_t)b * GSTRIDE + q];

            float4 gA = t0[q];
            float4 gB = t1[q];
            float4 gC = t2[q];
            float4 gD = t3[q];

            float xA = sp + gA.x; float wA = ex2f_fast(fmaxf(xA, 0.2f * xA));
            float xB = sp + gB.x; float wB = ex2f_fast(fmaxf(xB, 0.2f * xB));
            float xC = sp + gC.x; float wC = ex2f_fast(fmaxf(xC, 0.2f * xC));
            float xD = sp + gD.x; float wD = ex2f_fast(fmaxf(xD, 0.2f * xD));

#pragma unroll
            for (int b = 0; b < N_GRAPH; ++b) {
                float wx = maskf(m[b].x, wA);
                float wy = maskf(m[b].y, wB);
                float wz = maskf(m[b].z, wC);
                float ww = maskf(m[b].w, wD);
                sum[b] += (wx + wy) + (wz + ww);
                a0[b] = fmaf(wx, gA.y, a0[b]); a0[b] = fmaf(wy, gB.y, a0[b]);
                a0[b] = fmaf(wz, gC.y, a0[b]); a0[b] = fmaf(ww, gD.y, a0[b]);
                a1[b] = fmaf(wx, gA.z, a1[b]); a1[b] = fmaf(wy, gB.z, a1[b]);
                a1[b] = fmaf(wz, gC.z, a1[b]); a1[b] = fmaf(ww, gD.z, a1[b]);
                a2[b] = fmaf(wx, gA.w, a2[b]); a2[b] = fmaf(wy, gB.w, a2[b]);
                a2[b] = fmaf(wz, gC.w, a2[b]); a2[b] = fmaf(ww, gD.w, a2[b]);
            }
        }

#pragma unroll
        for (int b = 0; b < N_GRAPH; ++b) {
#pragma unroll
            for (int off = 16; off; off >>= 1) {
                sum[b] += __shfl_xor_sync(0xffffffffu, sum[b], off);
                a0[b]  += __shfl_xor_sync(0xffffffffu, a0[b],  off);
                a1[b]  += __shfl_xor_sync(0xffffffffu, a1[b],  off);
                a2[b]  += __shfl_xor_sync(0xffffffffu, a2[b],  off);
            }
        }

        if (lane == 0) {
#pragma unroll
            for (int b = 0; b < N_GRAPH; ++b) {
                float* hp = g_h + (size_t)b * KTOT + (size_t)i * 3;
                if (sum[b] == 0.0f) {
                    hp[0] = __ldg(&g_fallback[0]);
                    hp[1] = __ldg(&g_fallback[1]);
                    hp[2] = __ldg(&g_fallback[2]);
                } else {
                    float inv = 1.0f / sum[b];
                    float h0 = a0[b] * inv, h1 = a1[b] * inv, h2 = a2[b] * inv;
                    hp[0] = h0 > 0.f ? h0 : expm1f(h0);
                    hp[1] = h1 > 0.f ? h1 : expm1f(h1);
                    hp[2] = h2 > 0.f ? h2 : expm1f(h2);
                }
            }
        }
    }
}

// ---------------------------------------------------------------------------
// Kernel 4a: fc partials. block (o, chunk): partial over k in chunk.
// ---------------------------------------------------------------------------
__global__ void __launch_bounds__(128)
fc_part_kernel(const float* __restrict__ fw) {
    int o = blockIdx.x;               // 0..99
    int c = blockIdx.y;               // 0..7
    int k0 = c * KCHUNK;
    const float* wrow = fw + (size_t)o * KTOT;

    float acc[N_GRAPH];
#pragma unroll
    for (int b = 0; b < N_GRAPH; ++b) acc[b] = 0.f;

#pragma unroll 4
    for (int kk = threadIdx.x; kk < KCHUNK; kk += 128) {
        int k = k0 + kk;
        float wv = __ldg(wrow + k);
#pragma unroll
        for (int b = 0; b < N_GRAPH; ++b)
            acc[b] = fmaf(wv, g_h[(size_t)b * KTOT + k], acc[b]);
    }

#pragma unroll
    for (int b = 0; b < N_GRAPH; ++b)
#pragma unroll
        for (int off = 16; off; off >>= 1)
            acc[b] += __shfl_xor_sync(0xffffffffu, acc[b], off);

    __shared__ float red[N_GRAPH][4];
    int lane = threadIdx.x & 31, w = threadIdx.x >> 5;
    if (lane == 0) {
#pragma unroll
        for (int b = 0; b < N_GRAPH; ++b) red[b][w] = acc[b];
    }
    __syncthreads();
    if (threadIdx.x < N_GRAPH) {
        int b = threadIdx.x;
        g_fcpart[((size_t)c * 100 + o) * N_GRAPH + b] =
            red[b][0] + red[b][1] + red[b][2] + red[b][3];
    }
}

// ---------------------------------------------------------------------------
// Kernel 4b: final sum over chunks + bias. 800 threads, one per (b,o).
// ---------------------------------------------------------------------------
__global__ void __launch_bounds__(800)
fc_final_kernel(const float* __restrict__ fb, float* __restrict__ out) {
    int t = threadIdx.x;              // 0..799
    int b = t / 100;
    int o = t - b * 100;
    float v = fb[o];
#pragma unroll
    for (int c = 0; c < 8; ++c)
        v += g_fcpart[((size_t)c * 100 + o) * N_GRAPH + b];
    out[b * 100 + o] = v;
}

// ---------------------------------------------------------------------------
extern "C" void kernel_launch(void* const* d_in, const int* in_sizes, int n_in,
                              void* d_out, int out_size) {
    const int*   adj = (const int*)d_in[0];
    const float* emb = (const float*)d_in[1];
    const float* W   = (const float*)d_in[2];
    const float* a   = (const float*)d_in[3];
    const float* fw  = (const float*)d_in[4];
    const float* fb  = (const float*)d_in[5];
    float* out = (float*)d_out;

    cudaFuncSetAttribute(gat8_kernel, cudaFuncAttributeMaxDynamicSharedMemorySize, 65536);

    prep_kernel<<<64, 256>>>(emb, W, a);
    mean_kernel<<<1, 256>>>();
    gat8_kernel<<<256, 256, 65536>>>(adj);
    fc_part_kernel<<<dim3(100, 8), 128>>>(fw);
    fc_final_kernel<<<1, 800>>>(fb, out);
}

// round 5
// speedup vs baseline: 1.3505x; 1.0173x over previous
#include <cuda_runtime.h>
#include <math.h>

#define N_NODES 4096
#define N_GRAPH 8
#define LOG2E   1.4426950408889634f
#define GSTRIDE 4194304   // int4 elements per graph (4096*4096/4)
#define KTOT    (N_NODES * 3)   // 12288
#define KCHUNK  1536            // KTOT / 8
#define GAT_BLOCKS 296          // 2 per SM on 148 SMs, balanced

// Persistent scratch (no allocations allowed).
__device__ float4 g_table[N_NODES];           // swizzled: [(j&3)*1024 + (j>>2)] = (d'_j, Wh0, Wh1, Wh2)
__device__ float  g_sprime[N_NODES];          // s_i * log2(e)
__device__ float  g_fallback[3];              // elu(mean_j Wh_j) for all-masked rows
__device__ float  g_h[N_GRAPH * KTOT];        // elu(attn @ Wh), [B][N*3]
__device__ float  g_fcpart[8 * 100 * N_GRAPH];// [chunk][o][b]

__device__ __forceinline__ float ex2f_fast(float x) {
    float r; asm("ex2.approx.ftz.f32 %0, %1;" : "=f"(r) : "f"(x)); return r;
}
__device__ __forceinline__ float maskf(int m, float w) {
    return __int_as_float((-m) & __float_as_int(w));
}

// ---------------------------------------------------------------------------
// Kernel 1: Wh = emb @ W, s,d, build swizzled table. 4 lanes per node.
// ---------------------------------------------------------------------------
__global__ void __launch_bounds__(256)
prep_kernel(const float* __restrict__ emb,
            const float* __restrict__ W,
            const float* __restrict__ a) {
    __shared__ float sW[384];
    __shared__ float sa[6];
    int tid = threadIdx.x;
    for (int k = tid; k < 384; k += 256) sW[k] = W[k];
    if (tid < 6) sa[tid] = a[tid];
    __syncthreads();

    int t  = blockIdx.x * 256 + tid;      // 0..16383
    int i  = t >> 2;                      // node
    int qd = t & 3;                       // quarter of the feature dim
    const float4* e4 = reinterpret_cast<const float4*>(emb + (size_t)i * 128) + qd * 8;
    float w0 = 0.f, w1 = 0.f, w2 = 0.f;
#pragma unroll
    for (int f4 = 0; f4 < 8; ++f4) {
        float4 e = e4[f4];
        int f = (qd * 8 + f4) * 4;
        w0 = fmaf(e.x, sW[(f+0)*3+0], w0); w1 = fmaf(e.x, sW[(f+0)*3+1], w1); w2 = fmaf(e.x, sW[(f+0)*3+2], w2);
        w0 = fmaf(e.y, sW[(f+1)*3+0], w0); w1 = fmaf(e.y, sW[(f+1)*3+1], w1); w2 = fmaf(e.y, sW[(f+1)*3+2], w2);
        w0 = fmaf(e.z, sW[(f+2)*3+0], w0); w1 = fmaf(e.z, sW[(f+2)*3+1], w1); w2 = fmaf(e.z, sW[(f+2)*3+2], w2);
        w0 = fmaf(e.w, sW[(f+3)*3+0], w0); w1 = fmaf(e.w, sW[(f+3)*3+1], w1); w2 = fmaf(e.w, sW[(f+3)*3+2], w2);
    }
#pragma unroll
    for (int off = 1; off <= 2; off <<= 1) {
        w0 += __shfl_xor_sync(0xffffffffu, w0, off);
        w1 += __shfl_xor_sync(0xffffffffu, w1, off);
        w2 += __shfl_xor_sync(0xffffffffu, w2, off);
    }
    if (qd == 0) {
        float s = w0*sa[0] + w1*sa[1] + w2*sa[2];
        float d = w0*sa[3] + w1*sa[4] + w2*sa[5];
        g_sprime[i] = s * LOG2E;
        g_table[(i & 3) * 1024 + (i >> 2)] = make_float4(d * LOG2E, w0, w1, w2);
    }
}

// ---------------------------------------------------------------------------
// Kernel 2: fallback for all-masked rows: elu(mean_j Wh_j)
// ---------------------------------------------------------------------------
__global__ void __launch_bounds__(256)
mean_kernel() {
    int tid = threadIdx.x;
    float m0 = 0.f, m1 = 0.f, m2 = 0.f;
    for (int idx = tid; idx < N_NODES; idx += 256) {
        float4 g = g_table[idx];
        m0 += g.y; m1 += g.z; m2 += g.w;
    }
#pragma unroll
    for (int off = 16; off; off >>= 1) {
        m0 += __shfl_xor_sync(0xffffffffu, m0, off);
        m1 += __shfl_xor_sync(0xffffffffu, m1, off);
        m2 += __shfl_xor_sync(0xffffffffu, m2, off);
    }
    __shared__ float red[3][8];
    int lane = tid & 31, w = tid >> 5;
    if (lane == 0) { red[0][w] = m0; red[1][w] = m1; red[2][w] = m2; }
    __syncthreads();
    if (tid == 0) {
        float t0 = 0.f, t1 = 0.f, t2 = 0.f;
#pragma unroll
        for (int k = 0; k < 8; ++k) { t0 += red[0][k]; t1 += red[1][k]; t2 += red[2][k]; }
        t0 *= (1.0f / N_NODES); t1 *= (1.0f / N_NODES); t2 *= (1.0f / N_NODES);
        g_fallback[0] = t0 > 0.f ? t0 : expm1f(t0);
        g_fallback[1] = t1 > 0.f ? t1 : expm1f(t1);
        g_fallback[2] = t2 > 0.f ? t2 : expm1f(t2);
    }
}

// ---------------------------------------------------------------------------
// Kernel 3: fused GAT. One warp per node-row i, ALL 8 graphs at once.
// Balanced grid: 296 CTAs (2/SM), per-CTA contiguous 13-14 row range.
// ---------------------------------------------------------------------------
__global__ void __launch_bounds__(256, 2)
gat8_kernel(const int* __restrict__ adj) {
    extern __shared__ float4 tbl[];   // 4096 float4 = 64 KB
    int tid = threadIdx.x;
    for (int idx = tid; idx < N_NODES; idx += 256)
        tbl[idx] = g_table[idx];
    __syncthreads();

    const float4* t0 = tbl;
    const float4* t1 = tbl + 1024;
    const float4* t2 = tbl + 2048;
    const float4* t3 = tbl + 3072;

    int lane = tid & 31;
    int warp = tid >> 5;

    // 4096 = 248*14 + 48*13: blocks <248 own 14 rows, rest own 13.
    int bid = blockIdx.x;
    int extra = bid < 248 ? bid : 248;
    int start = bid * 13 + extra;
    int count = 13 + (bid < 248 ? 1 : 0);

    for (int r = warp; r < count; r += 8) {
        int i = start + r;
        float sp = __ldg(&g_sprime[i]);
        const int4* arow = reinterpret_cast<const int4*>(adj) + (size_t)i * 1024;

        float sum[N_GRAPH], a0[N_GRAPH], a1[N_GRAPH], a2[N_GRAPH];
#pragma unroll
        for (int b = 0; b < N_GRAPH; ++b) { sum[b] = 0.f; a0[b] = 0.f; a1[b] = 0.f; a2[b] = 0.f; }

        for (int q = lane; q < 1024; q += 32) {
            int4 m[N_GRAPH];
#pragma unroll
            for (int b = 0; b < N_GRAPH; ++b)
                m[b] = arow[(size_t)b * GSTRIDE + q];

            float4 gA = t0[q];
            float4 gB = t1[q];
            float4 gC = t2[q];
            float4 gD = t3[q];

            float xA = sp + gA.x; float wA = ex2f_fast(fmaxf(xA, 0.2f * xA));
            float xB = sp + gB.x; float wB = ex2f_fast(fmaxf(xB, 0.2f * xB));
            float xC = sp + gC.x; float wC = ex2f_fast(fmaxf(xC, 0.2f * xC));
            float xD = sp + gD.x; float wD = ex2f_fast(fmaxf(xD, 0.2f * xD));

#pragma unroll
            for (int b = 0; b < N_GRAPH; ++b) {
                float wx = maskf(m[b].x, wA);
                float wy = maskf(m[b].y, wB);
                float wz = maskf(m[b].z, wC);
                float ww = maskf(m[b].w, wD);
                sum[b] += (wx + wy) + (wz + ww);
                a0[b] = fmaf(wx, gA.y, a0[b]); a0[b] = fmaf(wy, gB.y, a0[b]);
                a0[b] = fmaf(wz, gC.y, a0[b]); a0[b] = fmaf(ww, gD.y, a0[b]);
                a1[b] = fmaf(wx, gA.z, a1[b]); a1[b] = fmaf(wy, gB.z, a1[b]);
                a1[b] = fmaf(wz, gC.z, a1[b]); a1[b] = fmaf(ww, gD.z, a1[b]);
                a2[b] = fmaf(wx, gA.w, a2[b]); a2[b] = fmaf(wy, gB.w, a2[b]);
                a2[b] = fmaf(wz, gC.w, a2[b]); a2[b] = fmaf(ww, gD.w, a2[b]);
            }
        }

#pragma unroll
        for (int b = 0; b < N_GRAPH; ++b) {
#pragma unroll
            for (int off = 16; off; off >>= 1) {
                sum[b] += __shfl_xor_sync(0xffffffffu, sum[b], off);
                a0[b]  += __shfl_xor_sync(0xffffffffu, a0[b],  off);
                a1[b]  += __shfl_xor_sync(0xffffffffu, a1[b],  off);
                a2[b]  += __shfl_xor_sync(0xffffffffu, a2[b],  off);
            }
        }

        if (lane == 0) {
#pragma unroll
            for (int b = 0; b < N_GRAPH; ++b) {
                float* hp = g_h + (size_t)b * KTOT + (size_t)i * 3;
                if (sum[b] == 0.0f) {
                    hp[0] = __ldg(&g_fallback[0]);
                    hp[1] = __ldg(&g_fallback[1]);
                    hp[2] = __ldg(&g_fallback[2]);
                } else {
                    float inv = 1.0f / sum[b];
                    float h0 = a0[b] * inv, h1 = a1[b] * inv, h2 = a2[b] * inv;
                    hp[0] = h0 > 0.f ? h0 : expm1f(h0);
                    hp[1] = h1 > 0.f ? h1 : expm1f(h1);
                    hp[2] = h2 > 0.f ? h2 : expm1f(h2);
                }
            }
        }
    }
}

// ---------------------------------------------------------------------------
// Kernel 4a: fc partials, float4-vectorized. block (o, chunk).
// ---------------------------------------------------------------------------
__global__ void __launch_bounds__(128)
fc_part_kernel(const float* __restrict__ fw) {
    int o = blockIdx.x;               // 0..99
    int c = blockIdx.y;               // 0..7
    const float4* wrow4 = reinterpret_cast<const float4*>(fw + (size_t)o * KTOT) + c * (KCHUNK / 4);

    float acc[N_GRAPH];
#pragma unroll
    for (int b = 0; b < N_GRAPH; ++b) acc[b] = 0.f;

#pragma unroll
    for (int s = 0; s < 3; ++s) {                 // 384 float4 / 128 threads
        int kk = s * 128 + threadIdx.x;
        float4 wv = __ldg(wrow4 + kk);
#pragma unroll
        for (int b = 0; b < N_GRAPH; ++b) {
            const float4* gh4 = reinterpret_cast<const float4*>(g_h + (size_t)b * KTOT) + c * (KCHUNK / 4);
            float4 hv = gh4[kk];
            acc[b] = fmaf(wv.x, hv.x, acc[b]);
            acc[b] = fmaf(wv.y, hv.y, acc[b]);
            acc[b] = fmaf(wv.z, hv.z, acc[b]);
            acc[b] = fmaf(wv.w, hv.w, acc[b]);
        }
    }

#pragma unroll
    for (int b = 0; b < N_GRAPH; ++b)
#pragma unroll
        for (int off = 16; off; off >>= 1)
            acc[b] += __shfl_xor_sync(0xffffffffu, acc[b], off);

    __shared__ float red[N_GRAPH][4];
    int lane = threadIdx.x & 31, w = threadIdx.x >> 5;
    if (lane == 0) {
#pragma unroll
        for (int b = 0; b < N_GRAPH; ++b) red[b][w] = acc[b];
    }
    __syncthreads();
    if (threadIdx.x < N_GRAPH) {
        int b = threadIdx.x;
        g_fcpart[((size_t)c * 100 + o) * N_GRAPH + b] =
            red[b][0] + red[b][1] + red[b][2] + red[b][3];
    }
}

// ---------------------------------------------------------------------------
// Kernel 4b: final sum over chunks + bias. 800 threads, one per (b,o).
// ---------------------------------------------------------------------------
__global__ void __launch_bounds__(800)
fc_final_kernel(const float* __restrict__ fb, float* __restrict__ out) {
    int t = threadIdx.x;              // 0..799
    int b = t / 100;
    int o = t - b * 100;
    float v = fb[o];
#pragma unroll
    for (int c = 0; c < 8; ++c)
        v += g_fcpart[((size_t)c * 100 + o) * N_GRAPH + b];
    out[b * 100 + o] = v;
}

// ---------------------------------------------------------------------------
extern "C" void kernel_launch(void* const* d_in, const int* in_sizes, int n_in,
                              void* d_out, int out_size) {
    const int*   adj = (const int*)d_in[0];
    const float* emb = (const float*)d_in[1];
    const float* W   = (const float*)d_in[2];
    const float* a   = (const float*)d_in[3];
    const float* fw  = (const float*)d_in[4];
    const float* fb  = (const float*)d_in[5];
    float* out = (float*)d_out;

    cudaFuncSetAttribute(gat8_kernel, cudaFuncAttributeMaxDynamicSharedMemorySize, 65536);

    prep_kernel<<<64, 256>>>(emb, W, a);
    mean_kernel<<<1, 256>>>();
    gat8_kernel<<<GAT_BLOCKS, 256, 65536>>>(adj);
    fc_part_kernel<<<dim3(100, 8), 128>>>(fw);
    fc_final_kernel<<<1, 800>>>(fb, out);
}

// round 6
// speedup vs baseline: 1.4728x; 1.0906x over previous
#include <cuda_runtime.h>
#include <math.h>

#define N_NODES 4096
#define N_GRAPH 8
#define LOG2E   1.4426950408889634f
#define GSTRIDE 4194304   // int4 elements per graph (4096*4096/4)
#define KTOT    (N_NODES * 3)   // 12288
#define KCHUNK  1536            // KTOT / 8
#define GAT_BLOCKS 296          // 2 per SM on 148 SMs
#define NWARPS   (GAT_BLOCKS * 8)   // 2368; 2368*256 == 37*16384 exactly

// Persistent scratch (no allocations allowed).
__device__ float4 g_table[N_NODES];           // swizzled: [(j&3)*1024 + (j>>2)] = (d'_j, Wh0, Wh1, Wh2)
__device__ float  g_sprime[N_NODES];          // s_i * log2(e)
__device__ float  g_fallback[3];              // elu(mean_j Wh_j) for all-masked rows
__device__ float4 g_part[N_NODES][2][N_GRAPH];// per-row partials: (sum, a0, a1, a2) per graph
__device__ float  g_h[N_GRAPH * KTOT];        // elu(attn @ Wh), [B][N*3]
__device__ float  g_fcpart[8 * 100 * N_GRAPH];// [chunk][o][b]

__device__ __forceinline__ float ex2f_fast(float x) {
    float r; asm("ex2.approx.ftz.f32 %0, %1;" : "=f"(r) : "f"(x)); return r;
}
__device__ __forceinline__ float maskf(int m, float w) {
    return __int_as_float((-m) & __float_as_int(w));
}

// ---------------------------------------------------------------------------
// Kernel 1: Wh = emb @ W, s,d, build swizzled table. 4 lanes per node.
// ---------------------------------------------------------------------------
__global__ void __launch_bounds__(256)
prep_kernel(const float* __restrict__ emb,
            const float* __restrict__ W,
            const float* __restrict__ a) {
    __shared__ float sW[384];
    __shared__ float sa[6];
    int tid = threadIdx.x;
    for (int k = tid; k < 384; k += 256) sW[k] = W[k];
    if (tid < 6) sa[tid] = a[tid];
    __syncthreads();

    int t  = blockIdx.x * 256 + tid;      // 0..16383
    int i  = t >> 2;                      // node
    int qd = t & 3;                       // quarter of the feature dim
    const float4* e4 = reinterpret_cast<const float4*>(emb + (size_t)i * 128) + qd * 8;
    float w0 = 0.f, w1 = 0.f, w2 = 0.f;
#pragma unroll
    for (int f4 = 0; f4 < 8; ++f4) {
        float4 e = e4[f4];
        int f = (qd * 8 + f4) * 4;
        w0 = fmaf(e.x, sW[(f+0)*3+0], w0); w1 = fmaf(e.x, sW[(f+0)*3+1], w1); w2 = fmaf(e.x, sW[(f+0)*3+2], w2);
        w0 = fmaf(e.y, sW[(f+1)*3+0], w0); w1 = fmaf(e.y, sW[(f+1)*3+1], w1); w2 = fmaf(e.y, sW[(f+1)*3+2], w2);
        w0 = fmaf(e.z, sW[(f+2)*3+0], w0); w1 = fmaf(e.z, sW[(f+2)*3+1], w1); w2 = fmaf(e.z, sW[(f+2)*3+2], w2);
        w0 = fmaf(e.w, sW[(f+3)*3+0], w0); w1 = fmaf(e.w, sW[(f+3)*3+1], w1); w2 = fmaf(e.w, sW[(f+3)*3+2], w2);
    }
#pragma unroll
    for (int off = 1; off <= 2; off <<= 1) {
        w0 += __shfl_xor_sync(0xffffffffu, w0, off);
        w1 += __shfl_xor_sync(0xffffffffu, w1, off);
        w2 += __shfl_xor_sync(0xffffffffu, w2, off);
    }
    if (qd == 0) {
        float s = w0*sa[0] + w1*sa[1] + w2*sa[2];
        float d = w0*sa[3] + w1*sa[4] + w2*sa[5];
        g_sprime[i] = s * LOG2E;
        g_table[(i & 3) * 1024 + (i >> 2)] = make_float4(d * LOG2E, w0, w1, w2);
    }
}

// ---------------------------------------------------------------------------
// Kernel 2: fallback for all-masked rows: elu(mean_j Wh_j)
// ---------------------------------------------------------------------------
__global__ void __launch_bounds__(256)
mean_kernel() {
    int tid = threadIdx.x;
    float m0 = 0.f, m1 = 0.f, m2 = 0.f;
    for (int idx = tid; idx < N_NODES; idx += 256) {
        float4 g = g_table[idx];
        m0 += g.y; m1 += g.z; m2 += g.w;
    }
#pragma unroll
    for (int off = 16; off; off >>= 1) {
        m0 += __shfl_xor_sync(0xffffffffu, m0, off);
        m1 += __shfl_xor_sync(0xffffffffu, m1, off);
        m2 += __shfl_xor_sync(0xffffffffu, m2, off);
    }
    __shared__ float red[3][8];
    int lane = tid & 31, w = tid >> 5;
    if (lane == 0) { red[0][w] = m0; red[1][w] = m1; red[2][w] = m2; }
    __syncthreads();
    if (tid == 0) {
        float t0 = 0.f, t1 = 0.f, t2 = 0.f;
#pragma unroll
        for (int k = 0; k < 8; ++k) { t0 += red[0][k]; t1 += red[1][k]; t2 += red[2][k]; }
        t0 *= (1.0f / N_NODES); t1 *= (1.0f / N_NODES); t2 *= (1.0f / N_NODES);
        g_fallback[0] = t0 > 0.f ? t0 : expm1f(t0);
        g_fallback[1] = t1 > 0.f ? t1 : expm1f(t1);
        g_fallback[2] = t2 > 0.f ? t2 : expm1f(t2);
    }
}

// ---------------------------------------------------------------------------
// Kernel 3: fused GAT, exactly balanced. 16384 quarter-rows over 2368 warps
// (6-7 quarters each). Each row touched by <=2 warps; partials to fixed slots.
// ---------------------------------------------------------------------------
__global__ void __launch_bounds__(256, 2)
gat8_kernel(const int* __restrict__ adj) {
    extern __shared__ float4 tbl[];   // 4096 float4 = 64 KB
    int tid = threadIdx.x;
    for (int idx = tid; idx < N_NODES; idx += 256)
        tbl[idx] = g_table[idx];
    __syncthreads();

    const float4* t0 = tbl;
    const float4* t1 = tbl + 1024;
    const float4* t2 = tbl + 2048;
    const float4* t3 = tbl + 3072;

    int lane = tid & 31;
    int w = blockIdx.x * 8 + (tid >> 5);          // 0..2367
    int qi = (w * 256 + 36) / 37;                 // quarter range [qi, qe)
    int qe = ((w + 1) * 256 + 36) / 37;

    const int4* adj4 = reinterpret_cast<const int4*>(adj);

    while (qi < qe) {
        int r = qi >> 2;
        int rowEnd = min(qe, (r + 1) << 2);
        int q0 = (qi - (r << 2)) << 8;            // start int4-index within row
        int q1 = (rowEnd - (r << 2)) << 8;        // end

        float sp = __ldg(&g_sprime[r]);
        const int4* arow = adj4 + (size_t)r * 1024;

        float sum[N_GRAPH], a0[N_GRAPH], a1[N_GRAPH], a2[N_GRAPH];
#pragma unroll
        for (int b = 0; b < N_GRAPH; ++b) { sum[b] = 0.f; a0[b] = 0.f; a1[b] = 0.f; a2[b] = 0.f; }

        for (int q = q0 + lane; q < q1; q += 32) {
            int4 m[N_GRAPH];
#pragma unroll
            for (int b = 0; b < N_GRAPH; ++b)
                m[b] = __ldcs(arow + (size_t)b * GSTRIDE + q);

            float4 gA = t0[q];
            float4 gB = t1[q];
            float4 gC = t2[q];
            float4 gD = t3[q];

            float xA = sp + gA.x; float wA = ex2f_fast(fmaxf(xA, 0.2f * xA));
            float xB = sp + gB.x; float wB = ex2f_fast(fmaxf(xB, 0.2f * xB));
            float xC = sp + gC.x; float wC = ex2f_fast(fmaxf(xC, 0.2f * xC));
            float xD = sp + gD.x; float wD = ex2f_fast(fmaxf(xD, 0.2f * xD));

#pragma unroll
            for (int b = 0; b < N_GRAPH; ++b) {
                float wx = maskf(m[b].x, wA);
                float wy = maskf(m[b].y, wB);
                float wz = maskf(m[b].z, wC);
                float ww = maskf(m[b].w, wD);
                sum[b] += (wx + wy) + (wz + ww);
                a0[b] = fmaf(wx, gA.y, a0[b]); a0[b] = fmaf(wy, gB.y, a0[b]);
                a0[b] = fmaf(wz, gC.y, a0[b]); a0[b] = fmaf(ww, gD.y, a0[b]);
                a1[b] = fmaf(wx, gA.z, a1[b]); a1[b] = fmaf(wy, gB.z, a1[b]);
                a1[b] = fmaf(wz, gC.z, a1[b]); a1[b] = fmaf(ww, gD.z, a1[b]);
                a2[b] = fmaf(wx, gA.w, a2[b]); a2[b] = fmaf(wy, gB.w, a2[b]);
                a2[b] = fmaf(wz, gC.w, a2[b]); a2[b] = fmaf(ww, gD.w, a2[b]);
            }
        }

#pragma unroll
        for (int b = 0; b < N_GRAPH; ++b) {
#pragma unroll
            for (int off = 16; off; off >>= 1) {
                sum[b] += __shfl_xor_sync(0xffffffffu, sum[b], off);
                a0[b]  += __shfl_xor_sync(0xffffffffu, a0[b],  off);
                a1[b]  += __shfl_xor_sync(0xffffffffu, a1[b],  off);
                a2[b]  += __shfl_xor_sync(0xffffffffu, a2[b],  off);
            }
        }

        if (lane == 0) {
            int slot = (qi == (r << 2)) ? 0 : 1;  // own the row's first quarter?
            float4* pp = &g_part[r][slot][0];
#pragma unroll
            for (int b = 0; b < N_GRAPH; ++b)
                pp[b] = make_float4(sum[b], a0[b], a1[b], a2[b]);
        }
        qi = rowEnd;
    }
}

// ---------------------------------------------------------------------------
// Kernel 3b: combine partials, normalize, elu. One thread per (row, graph).
// ---------------------------------------------------------------------------
__global__ void __launch_bounds__(256)
combine_kernel() {
    int idx = blockIdx.x * 256 + threadIdx.x;     // 0..32767
    int r = idx >> 3;
    int b = idx & 7;
    int w0 = ((r << 2) * 37) >> 8;                // warp covering first quarter
    int w3 = (((r << 2) + 3) * 37) >> 8;          // warp covering last quarter
    float4 p = g_part[r][0][b];
    if (w0 != w3) {                               // row split across two warps
        float4 p1 = g_part[r][1][b];
        p.x += p1.x; p.y += p1.y; p.z += p1.z; p.w += p1.w;
    }
    float h0, h1, h2;
    if (p.x == 0.0f) {
        h0 = g_fallback[0]; h1 = g_fallback[1]; h2 = g_fallback[2];
    } else {
        float inv = 1.0f / p.x;
        h0 = p.y * inv; h1 = p.z * inv; h2 = p.w * inv;
        h0 = h0 > 0.f ? h0 : expm1f(h0);
        h1 = h1 > 0.f ? h1 : expm1f(h1);
        h2 = h2 > 0.f ? h2 : expm1f(h2);
    }
    float* hp = g_h + (size_t)b * KTOT + (size_t)r * 3;
    hp[0] = h0; hp[1] = h1; hp[2] = h2;
}

// ---------------------------------------------------------------------------
// Kernel 4a: fc partials, 2 outputs per block. block (o-pair, chunk).
// ---------------------------------------------------------------------------
__global__ void __launch_bounds__(128)
fc_part_kernel(const float* __restrict__ fw) {
    int o0 = blockIdx.x * 2;          // 0,2,..,98
    int c  = blockIdx.y;              // 0..7
    const float4* wA4 = reinterpret_cast<const float4*>(fw + (size_t)o0 * KTOT) + c * (KCHUNK / 4);
    const float4* wB4 = reinterpret_cast<const float4*>(fw + (size_t)(o0 + 1) * KTOT) + c * (KCHUNK / 4);

    float acc[2][N_GRAPH];
#pragma unroll
    for (int b = 0; b < N_GRAPH; ++b) { acc[0][b] = 0.f; acc[1][b] = 0.f; }

#pragma unroll
    for (int s = 0; s < 3; ++s) {                 // 384 float4 / 128 threads
        int kk = s * 128 + threadIdx.x;
        float4 wa = __ldg(wA4 + kk);
        float4 wb = __ldg(wB4 + kk);
#pragma unroll
        for (int b = 0; b < N_GRAPH; ++b) {
            const float4* gh4 = reinterpret_cast<const float4*>(g_h + (size_t)b * KTOT) + c * (KCHUNK / 4);
            float4 hv = gh4[kk];
            acc[0][b] = fmaf(wa.x, hv.x, acc[0][b]);
            acc[0][b] = fmaf(wa.y, hv.y, acc[0][b]);
            acc[0][b] = fmaf(wa.z, hv.z, acc[0][b]);
            acc[0][b] = fmaf(wa.w, hv.w, acc[0][b]);
            acc[1][b] = fmaf(wb.x, hv.x, acc[1][b]);
            acc[1][b] = fmaf(wb.y, hv.y, acc[1][b]);
            acc[1][b] = fmaf(wb.z, hv.z, acc[1][b]);
            acc[1][b] = fmaf(wb.w, hv.w, acc[1][b]);
        }
    }

#pragma unroll
    for (int oo = 0; oo < 2; ++oo)
#pragma unroll
        for (int b = 0; b < N_GRAPH; ++b)
#pragma unroll
            for (int off = 16; off; off >>= 1)
                acc[oo][b] += __shfl_xor_sync(0xffffffffu, acc[oo][b], off);

    __shared__ float red[4][16];
    int lane = threadIdx.x & 31, w = threadIdx.x >> 5;
    if (lane == 0) {
#pragma unroll
        for (int oo = 0; oo < 2; ++oo)
#pragma unroll
            for (int b = 0; b < N_GRAPH; ++b)
                red[w][oo * 8 + b] = acc[oo][b];
    }
    __syncthreads();
    if (threadIdx.x < 16) {
        int oo = threadIdx.x >> 3, b = threadIdx.x & 7;
        float v = red[0][threadIdx.x] + red[1][threadIdx.x] +
                  red[2][threadIdx.x] + red[3][threadIdx.x];
        g_fcpart[((size_t)c * 100 + (o0 + oo)) * N_GRAPH + b] = v;
    }
}

// ---------------------------------------------------------------------------
// Kernel 4b: final sum over chunks + bias. 800 threads, one per (b,o).
// ---------------------------------------------------------------------------
__global__ void __launch_bounds__(800)
fc_final_kernel(const float* __restrict__ fb, float* __restrict__ out) {
    int t = threadIdx.x;              // 0..799
    int b = t / 100;
    int o = t - b * 100;
    float v = fb[o];
#pragma unroll
    for (int c = 0; c < 8; ++c)
        v += g_fcpart[((size_t)c * 100 + o) * N_GRAPH + b];
    out[b * 100 + o] = v;
}

// ---------------------------------------------------------------------------
extern "C" void kernel_launch(void* const* d_in, const int* in_sizes, int n_in,
                              void* d_out, int out_size) {
    const int*   adj = (const int*)d_in[0];
    const float* emb = (const float*)d_in[1];
    const float* W   = (const float*)d_in[2];
    const float* a   = (const float*)d_in[3];
    const float* fw  = (const float*)d_in[4];
    const float* fb  = (const float*)d_in[5];
    float* out = (float*)d_out;

    cudaFuncSetAttribute(gat8_kernel, cudaFuncAttributeMaxDynamicSharedMemorySize, 65536);

    prep_kernel<<<64, 256>>>(emb, W, a);
    mean_kernel<<<1, 256>>>();
    gat8_kernel<<<GAT_BLOCKS, 256, 65536>>>(adj);
    combine_kernel<<<128, 256>>>();
    fc_part_kernel<<<dim3(50, 8), 128>>>(fw);
    fc_final_kernel<<<1, 800>>>(fb, out);
}